// round 2
// baseline (speedup 1.0000x reference)
#include <cuda_runtime.h>

// ---------------- problem constants ----------------
#define NN 100000      // nodes
#define NE 3200000     // edges
#define NG 512         // graphs
#define BN_EPS 1e-5f

// ---------------- device scratch (no allocs allowed) ----------------
__device__ int      d_src[NE];
__device__ int      d_dst[NE];
__device__ float    d_deg[NN];
__device__ float    d_dis[NN];
__device__ float    d_agg[(size_t)NN * 32];     // max F_in = 32
__device__ float    d_y1 [(size_t)NN * 8];
__device__ float    d_y2 [(size_t)NN * 32];
__device__ float    d_y3 [(size_t)NN * 128];
__device__ float    d_stats[256];               // [0..127] sum, [128..255] sumsq
__device__ float    d_scale[128];
__device__ float    d_shift[128];
__device__ unsigned d_pool[NG * 128];
__device__ int      d_is64_edge;
__device__ int      d_is64_batch;

// ordered-uint encoding so atomicMax on unsigned == max on float
__device__ __forceinline__ unsigned f2o(float v) {
    unsigned u = __float_as_uint(v);
    return (u & 0x80000000u) ? ~u : (u | 0x80000000u);
}
__device__ __forceinline__ float o2f(unsigned u) {
    return (u & 0x80000000u) ? __uint_as_float(u & 0x7FFFFFFFu)
                             : __uint_as_float(~u);
}

// ---------------- dtype detection (int64 vs int32 indices) ----------------
__global__ void k_detect(const void* ei, const void* bi) {
    if (threadIdx.x == 0 && blockIdx.x == 0) {
        // If the buffer actually holds int32, an int64 view at spread offsets
        // will almost surely contain values >= 2^32 (hi half nonzero).
        const long long* e64 = (const long long*)ei;
        int ok = 1;
        for (int k = 0; k < 256; k++) {           // idx <= 1.53M < NE/2
            long long v = e64[k * 6000];
            if (v < 0 || v >= NN) { ok = 0; break; }
        }
        d_is64_edge = ok;
        const long long* b64 = (const long long*)bi;
        ok = 1;
        for (int k = 0; k < 256; k++) {           // idx <= 49725 < NN/2
            long long v = b64[k * 195];
            if (v < 0 || v >= NG) { ok = 0; break; }
        }
        d_is64_batch = ok;
    }
}

// ---------------- init: deg=1 (self loop), pool=-inf-encoded(0) ----------------
__global__ void k_init() {
    int i = blockIdx.x * blockDim.x + threadIdx.x;
    if (i < NN) d_deg[i] = 1.0f;
    if (i < NG * 128) d_pool[i] = 0u;
}

// ---------------- edge prep: int32 conversion + degree ----------------
__global__ void k_edges(const void* ei) {
    int e = blockIdx.x * blockDim.x + threadIdx.x;
    if (e >= NE) return;
    int s, d;
    if (d_is64_edge) {
        const long long* p = (const long long*)ei;
        s = (int)p[e];
        d = (int)p[(size_t)NE + e];
    } else {
        const int* p = (const int*)ei;
        s = p[e];
        d = p[NE + e];
    }
    d_src[e] = s;
    d_dst[e] = d;
    atomicAdd(&d_deg[d], 1.0f);
}

__global__ void k_dis() {
    int i = blockIdx.x * blockDim.x + threadIdx.x;
    if (i < NN) d_dis[i] = rsqrtf(d_deg[i]);   // deg >= 1 always
}

// ---------------- self-loop init of agg (+ stats zeroing) ----------------
// agg[i,f] = bn(h[i,f]) * dis[i]^2   (self-loop norm = 1/deg)
template <int F, bool BN>
__global__ void k_selfinit(const float* __restrict__ h) {
    int t = blockIdx.x * blockDim.x + threadIdx.x;
    if (t < 256) d_stats[t] = 0.0f;            // prep for this layer's k_stats
    if (t >= NN * F) return;
    int i = t / F, f = t % F;
    float v = h[t];
    if (BN) v = v * d_scale[f] + d_shift[f];
    float di = d_dis[i];
    d_agg[t] = v * di * di;
}

// ---------------- edge scatter: agg[dst] += bn(h[src]) * norm ----------------
template <int F, int TPE, bool BN>
__global__ void k_scatter(const float* __restrict__ h) {
    const int VEC = F / TPE;                   // 2 or 4
    int t = blockIdx.x * blockDim.x + threadIdx.x;
    int e = t / TPE;
    if (e >= NE) return;
    int part = t % TPE;
    int s = d_src[e], d = d_dst[e];
    float nm = d_dis[s] * d_dis[d];
    int cb = part * VEC;
    const float* hp = h + (size_t)s * F + cb;
    float v[4];
    if (VEC == 4) {
        float4 x4 = *(const float4*)hp;
        v[0] = x4.x; v[1] = x4.y; v[2] = x4.z; v[3] = x4.w;
    } else {
        float2 x2 = *(const float2*)hp;
        v[0] = x2.x; v[1] = x2.y; v[2] = 0.f; v[3] = 0.f;
    }
    float* o = d_agg + (size_t)d * F + cb;
#pragma unroll
    for (int k = 0; k < VEC; k++) {
        float val = v[k];
        if (BN) val = val * d_scale[cb + k] + d_shift[cb + k];
        atomicAdd(o + k, val * nm);
    }
}

// ---------------- per-node GEMM + bias + relu ----------------
template <int FI, int FO>
__global__ void k_gemm(const float* __restrict__ W, const float* __restrict__ b,
                       float* __restrict__ y) {
    __shared__ float sW[FI * FO];
    __shared__ float sb[FO];
    for (int k = threadIdx.x; k < FI * FO; k += blockDim.x) sW[k] = W[k];
    if (threadIdx.x < FO) sb[threadIdx.x] = b[threadIdx.x];
    __syncthreads();
    int i = blockIdx.x * blockDim.x + threadIdx.x;
    if (i >= NN) return;
    float a[FI];
#pragma unroll
    for (int f = 0; f < FI; f++) a[f] = d_agg[(size_t)i * FI + f];
    float* yo = y + (size_t)i * FO;
    for (int j = 0; j < FO; j += 4) {
        float4 acc = make_float4(sb[j], sb[j + 1], sb[j + 2], sb[j + 3]);
#pragma unroll
        for (int f = 0; f < FI; f++) {
            float av = a[f];
            const float* wr = &sW[f * FO + j];
            acc.x += av * wr[0];
            acc.y += av * wr[1];
            acc.z += av * wr[2];
            acc.w += av * wr[3];
        }
        acc.x = fmaxf(acc.x, 0.f); acc.y = fmaxf(acc.y, 0.f);
        acc.z = fmaxf(acc.z, 0.f); acc.w = fmaxf(acc.w, 0.f);
        *(float4*)(yo + j) = acc;
    }
}

// ---------------- BN stats: per-channel sum / sumsq ----------------
template <int FO>
__global__ void k_stats(const float* __restrict__ y) {
    constexpr int R = 256 / FO;
    __shared__ float ssum[256], ssq[256];
    int c = threadIdx.x % FO;
    int r = threadIdx.x / FO;
    float s = 0.f, q = 0.f;
    for (int i = blockIdx.x * R + r; i < NN; i += gridDim.x * R) {
        float v = y[(size_t)i * FO + c];
        s += v;
        q += v * v;
    }
    ssum[threadIdx.x] = s;
    ssq[threadIdx.x] = q;
    __syncthreads();
    if (r == 0) {
#pragma unroll
        for (int k = 1; k < R; k++) {
            s += ssum[k * FO + c];
            q += ssq[k * FO + c];
        }
        atomicAdd(&d_stats[c], s);
        atomicAdd(&d_stats[128 + c], q);
    }
}

template <int FO>
__global__ void k_bnparams(const float* __restrict__ gam,
                           const float* __restrict__ bet) {
    int c = threadIdx.x;
    if (c >= FO) return;
    float m   = d_stats[c] * (1.0f / NN);
    float var = d_stats[128 + c] * (1.0f / NN) - m * m;
    float sc  = gam[c] * rsqrtf(var + BN_EPS);
    d_scale[c] = sc;
    d_shift[c] = bet[c] - m * sc;
}

// ---------------- graph max-pool (BN applied on the fly) ----------------
__global__ void k_pool(const float* __restrict__ y3, const void* bi) {
    int t = blockIdx.x * blockDim.x + threadIdx.x;
    if (t >= NN * 128) return;
    int i = t >> 7, c = t & 127;
    float v = y3[t] * d_scale[c] + d_shift[c];
    int g;
    if (d_is64_batch) g = (int)((const long long*)bi)[i];
    else              g = ((const int*)bi)[i];
    atomicMax(&d_pool[g * 128 + c], f2o(v));
}

// ---------------- final linear + log_softmax ----------------
__global__ void k_final(const float* __restrict__ Wl, const float* __restrict__ bl,
                        float* __restrict__ out) {
    __shared__ float ssum[12];                 // 4 warps x 3
    int g = blockIdx.x, t = threadIdx.x;
    float p = o2f(d_pool[g * 128 + t]);
    float a0 = p * Wl[t * 3 + 0];
    float a1 = p * Wl[t * 3 + 1];
    float a2 = p * Wl[t * 3 + 2];
#pragma unroll
    for (int o = 16; o > 0; o >>= 1) {
        a0 += __shfl_down_sync(0xFFFFFFFFu, a0, o);
        a1 += __shfl_down_sync(0xFFFFFFFFu, a1, o);
        a2 += __shfl_down_sync(0xFFFFFFFFu, a2, o);
    }
    int w = t >> 5;
    if ((t & 31) == 0) { ssum[w * 3] = a0; ssum[w * 3 + 1] = a1; ssum[w * 3 + 2] = a2; }
    __syncthreads();
    if (t == 0) {
        float l0 = bl[0], l1 = bl[1], l2 = bl[2];
#pragma unroll
        for (int k = 0; k < 4; k++) {
            l0 += ssum[k * 3]; l1 += ssum[k * 3 + 1]; l2 += ssum[k * 3 + 2];
        }
        float mx = fmaxf(l0, fmaxf(l1, l2));
        float lse = mx + logf(expf(l0 - mx) + expf(l1 - mx) + expf(l2 - mx));
        out[g * 3 + 0] = l0 - lse;
        out[g * 3 + 1] = l1 - lse;
        out[g * 3 + 2] = l2 - lse;
    }
}

// ---------------- launcher ----------------
extern "C" void kernel_launch(void* const* d_in, const int* in_sizes, int n_in,
                              void* d_out, int out_size) {
    const float* x   = (const float*)d_in[0];
    const void*  ei  = d_in[1];
    const void*  bi  = d_in[2];
    const float* W1  = (const float*)d_in[3];
    const float* b1  = (const float*)d_in[4];
    const float* g1  = (const float*)d_in[5];
    const float* be1 = (const float*)d_in[6];
    const float* W2  = (const float*)d_in[7];
    const float* b2  = (const float*)d_in[8];
    const float* g2  = (const float*)d_in[9];
    const float* be2 = (const float*)d_in[10];
    const float* W3  = (const float*)d_in[11];
    const float* b3  = (const float*)d_in[12];
    const float* g3  = (const float*)d_in[13];
    const float* be3 = (const float*)d_in[14];
    const float* Wl  = (const float*)d_in[15];
    const float* bl  = (const float*)d_in[16];
    float* out = (float*)d_out;

    float *y1, *y2, *y3;
    cudaGetSymbolAddress((void**)&y1, d_y1);
    cudaGetSymbolAddress((void**)&y2, d_y2);
    cudaGetSymbolAddress((void**)&y3, d_y3);

    const int T = 256;
    k_detect<<<1, 32>>>(ei, bi);
    k_init<<<(NN + T - 1) / T, T>>>();
    k_edges<<<(NE + T - 1) / T, T>>>(ei);
    k_dis<<<(NN + T - 1) / T, T>>>();

    // layer 1: 2 -> 8 (no BN on input x)
    k_selfinit<2, false><<<(NN * 2 + T - 1) / T, T>>>(x);
    k_scatter<2, 1, false><<<(NE + T - 1) / T, T>>>(x);
    k_gemm<2, 8><<<(NN + T - 1) / T, T>>>(W1, b1, y1);
    k_stats<8><<<512, T>>>(y1);
    k_bnparams<8><<<1, 32>>>(g1, be1);

    // layer 2: 8 -> 32 (BN of layer 1 applied on the fly)
    k_selfinit<8, true><<<(NN * 8 + T - 1) / T, T>>>(y1);
    k_scatter<8, 2, true><<<(NE * 2 + T - 1) / T, T>>>(y1);
    k_gemm<8, 32><<<(NN + T - 1) / T, T>>>(W2, b2, y2);
    k_stats<32><<<512, T>>>(y2);
    k_bnparams<32><<<1, 32>>>(g2, be2);

    // layer 3: 32 -> 128 (BN of layer 2 applied on the fly)
    k_selfinit<32, true><<<(NN * 32 + T - 1) / T, T>>>(y2);
    {
        long long tot = (long long)NE * 8;
        k_scatter<32, 8, true><<<(unsigned)((tot + T - 1) / T), T>>>(y2);
    }
    k_gemm<32, 128><<<(NN + T - 1) / T, T>>>(W3, b3, y3);
    k_stats<128><<<512, T>>>(y3);
    k_bnparams<128><<<1, 128>>>(g3, be3);

    // pooling (BN of layer 3 applied on the fly) + final head
    {
        long long tot = (long long)NN * 128;
        k_pool<<<(unsigned)((tot + T - 1) / T), T>>>(y3, bi);
    }
    k_final<<<NG, 128>>>(Wl, bl, out);
}

// round 3
// speedup vs baseline: 1.5710x; 1.5710x over previous
#include <cuda_runtime.h>
#include <math_constants.h>

// ---------------- problem constants ----------------
#define NN 100000      // nodes
#define NE 3200000     // edges
#define NG 512         // graphs
#define BN_EPS 1e-5f
#define NBLK ((NN + 255) / 256)   // 391

// ---------------- device scratch (no allocs allowed) ----------------
__device__ int      d_cnt[NN];            // in-degree (excl self loop)
__device__ int      d_rowptr[NN + 1];
__device__ int      d_wp[NN];             // fill write pointers
__device__ int      d_bsum[512];
__device__ int      d_boff[512];
__device__ int      d_csr_src[NE];
__device__ float    d_csr_nrm[NE];
__device__ float    d_dis[NN];
__device__ float    d_agg[(size_t)NN * 32];
__device__ float    d_y1 [(size_t)NN * 8];
__device__ float    d_y2 [(size_t)NN * 32];
__device__ float    d_y3 [(size_t)NN * 128];
__device__ float    d_stats[256];         // [0..127] sum, [128..255] sumsq
__device__ float    d_scale[128];
__device__ float    d_shift[128];
__device__ float    d_pool[NG * 128];
__device__ int      d_gstart[NG];
__device__ int      d_gend[NG];
__device__ int      d_is64_edge;
__device__ int      d_is64_batch;

// ---------------- dtype detection (int64 vs int32 indices) ----------------
__global__ void k_detect(const void* ei, const void* bi) {
    if (threadIdx.x == 0 && blockIdx.x == 0) {
        const long long* e64 = (const long long*)ei;
        int ok = 1;
        for (int k = 0; k < 256; k++) {
            long long v = e64[k * 6000];
            if (v < 0 || v >= NN) { ok = 0; break; }
        }
        d_is64_edge = ok;
        const long long* b64 = (const long long*)bi;
        ok = 1;
        for (int k = 0; k < 256; k++) {
            long long v = b64[k * 195];
            if (v < 0 || v >= NG) { ok = 0; break; }
        }
        d_is64_batch = ok;
    }
}

// ---------------- init ----------------
__global__ void k_init() {
    int i = blockIdx.x * blockDim.x + threadIdx.x;
    if (i < NN) d_cnt[i] = 0;
    if (i < 256) d_stats[i] = 0.0f;
    if (i < NG) { d_gstart[i] = 0; d_gend[i] = 0; }
}

// ---------------- CSR build ----------------
__global__ void k_count(const void* ei) {
    int e = blockIdx.x * blockDim.x + threadIdx.x;
    if (e >= NE) return;
    int d;
    if (d_is64_edge) d = (int)((const long long*)ei)[(size_t)NE + e];
    else             d = ((const int*)ei)[NE + e];
    atomicAdd(&d_cnt[d], 1);
}

__global__ void k_scan1() {           // per-block sums
    __shared__ int s[256];
    int i = blockIdx.x * 256 + threadIdx.x;
    int v = (i < NN) ? d_cnt[i] : 0;
    s[threadIdx.x] = v;
    __syncthreads();
    for (int o = 128; o > 0; o >>= 1) {
        if (threadIdx.x < o) s[threadIdx.x] += s[threadIdx.x + o];
        __syncthreads();
    }
    if (threadIdx.x == 0) d_bsum[blockIdx.x] = s[0];
}

__global__ void k_scan2() {           // scan block sums (1 block, 512 thr)
    __shared__ int s[512];
    int t = threadIdx.x;
    int orig = (t < NBLK) ? d_bsum[t] : 0;
    s[t] = orig;
    __syncthreads();
    for (int o = 1; o < 512; o <<= 1) {
        int u = (t >= o) ? s[t - o] : 0;
        __syncthreads();
        s[t] += u;
        __syncthreads();
    }
    d_boff[t] = s[t] - orig;
}

__global__ void k_scan3() {           // rowptr + wp + dis
    __shared__ int s[256];
    int i = blockIdx.x * 256 + threadIdx.x;
    int orig = (i < NN) ? d_cnt[i] : 0;
    s[threadIdx.x] = orig;
    __syncthreads();
    for (int o = 1; o < 256; o <<= 1) {
        int u = (threadIdx.x >= o) ? s[threadIdx.x - o] : 0;
        __syncthreads();
        s[threadIdx.x] += u;
        __syncthreads();
    }
    int excl = s[threadIdx.x] - orig + d_boff[blockIdx.x];
    if (i < NN) {
        d_rowptr[i] = excl;
        d_wp[i] = excl;
        d_dis[i] = rsqrtf((float)(orig + 1));   // deg = in-degree + self loop
    }
    if (i == 0) d_rowptr[NN] = NE;
}

__global__ void k_fill(const void* ei) {
    int e = blockIdx.x * blockDim.x + threadIdx.x;
    if (e >= NE) return;
    int s, d;
    if (d_is64_edge) {
        const long long* p = (const long long*)ei;
        s = (int)p[e];
        d = (int)p[(size_t)NE + e];
    } else {
        const int* p = (const int*)ei;
        s = p[e];
        d = p[NE + e];
    }
    int pos = atomicAdd(&d_wp[d], 1);
    d_csr_src[pos] = s;
    d_csr_nrm[pos] = d_dis[s] * d_dis[d];
}

// ---------------- aggregation (gather, no atomics) ----------------
// layer 1: F=2, thread per node, no BN on input
__global__ void k_agg2(const float* __restrict__ x) {
    int i = blockIdx.x * blockDim.x + threadIdx.x;
    if (i >= NN) return;
    const float2* x2 = (const float2*)x;
    float di = d_dis[i];
    float2 self = x2[i];
    float ax = self.x * di * di, ay = self.y * di * di;
    int beg = d_rowptr[i], end = d_rowptr[i + 1];
    for (int e = beg; e < end; e++) {
        int s = d_csr_src[e];
        float nm = d_csr_nrm[e];
        float2 v = __ldg(&x2[s]);
        ax += v.x * nm;
        ay += v.y * nm;
    }
    float2* out = (float2*)d_agg;
    out[i] = make_float2(ax, ay);
}

// layer 2: F=8, 8 threads per node (BN of previous layer folded in)
__global__ void k_agg8(const float* __restrict__ h) {
    int t = blockIdx.x * blockDim.x + threadIdx.x;
    int node = t >> 3;
    if (node >= NN) return;
    int ln = t & 7;
    unsigned gm = 0xFFu << (((threadIdx.x & 31) >> 3) << 3);
    float sc = d_scale[ln], sh = d_shift[ln];
    float di = d_dis[node];
    float acc = (h[(size_t)node * 8 + ln] * sc + sh) * di * di;
    int beg = d_rowptr[node], end = d_rowptr[node + 1];
    for (int e0 = beg; e0 < end; e0 += 8) {
        int idx = e0 + ln;
        int s    = (idx < end) ? d_csr_src[idx] : 0;
        float nm = (idx < end) ? d_csr_nrm[idx] : 0.f;
#pragma unroll
        for (int j = 0; j < 8; j++) {
            int   ss = __shfl_sync(gm, s, j, 8);
            float nn = __shfl_sync(gm, nm, j, 8);
            float hv = __ldg(&h[(size_t)ss * 8 + ln]);
            acc += (hv * sc + sh) * nn;
        }
    }
    d_agg[(size_t)node * 8 + ln] = acc;
}

// layer 3: F=32, warp per node (BN of previous layer folded in)
__global__ void k_agg32(const float* __restrict__ h) {
    int w = (blockIdx.x * blockDim.x + threadIdx.x) >> 5;
    if (w >= NN) return;
    int lane = threadIdx.x & 31;
    float sc = d_scale[lane], sh = d_shift[lane];
    float di = d_dis[w];
    float acc = (h[(size_t)w * 32 + lane] * sc + sh) * di * di;
    int beg = d_rowptr[w], end = d_rowptr[w + 1];
    for (int e0 = beg; e0 < end; e0 += 32) {
        int idx = e0 + lane;
        int s    = (idx < end) ? d_csr_src[idx] : 0;
        float nm = (idx < end) ? d_csr_nrm[idx] : 0.f;
        int lim = end - e0;
        for (int j = 0; j < 32; j += 8) {
            if (j >= lim) break;
#pragma unroll
            for (int jj = 0; jj < 8; jj++) {
                int   ss = __shfl_sync(0xFFFFFFFFu, s, j + jj);
                float nn = __shfl_sync(0xFFFFFFFFu, nm, j + jj);
                float hv = __ldg(&h[(size_t)ss * 32 + lane]);
                acc += (hv * sc + sh) * nn;
            }
        }
    }
    d_agg[(size_t)w * 32 + lane] = acc;
}

// ---------------- per-node GEMM + bias + relu ----------------
template <int FI, int FO>
__global__ void k_gemm(const float* __restrict__ W, const float* __restrict__ b,
                       float* __restrict__ y) {
    __shared__ float sW[FI * FO];
    __shared__ float sb[FO];
    for (int k = threadIdx.x; k < FI * FO; k += blockDim.x) sW[k] = W[k];
    if (threadIdx.x < FO) sb[threadIdx.x] = b[threadIdx.x];
    __syncthreads();
    int i = blockIdx.x * blockDim.x + threadIdx.x;
    if (i >= NN) return;
    float a[FI];
#pragma unroll
    for (int f = 0; f < FI; f++) a[f] = d_agg[(size_t)i * FI + f];
    float* yo = y + (size_t)i * FO;
    for (int j = 0; j < FO; j += 4) {
        float4 acc = make_float4(sb[j], sb[j + 1], sb[j + 2], sb[j + 3]);
#pragma unroll
        for (int f = 0; f < FI; f++) {
            float av = a[f];
            const float* wr = &sW[f * FO + j];
            acc.x += av * wr[0];
            acc.y += av * wr[1];
            acc.z += av * wr[2];
            acc.w += av * wr[3];
        }
        acc.x = fmaxf(acc.x, 0.f); acc.y = fmaxf(acc.y, 0.f);
        acc.z = fmaxf(acc.z, 0.f); acc.w = fmaxf(acc.w, 0.f);
        *(float4*)(yo + j) = acc;
    }
}

// ---------------- BN stats ----------------
template <int FO>
__global__ void k_stats(const float* __restrict__ y) {
    constexpr int R = 256 / FO;
    __shared__ float ssum[256], ssq[256];
    int c = threadIdx.x % FO;
    int r = threadIdx.x / FO;
    float s = 0.f, q = 0.f;
    for (int i = blockIdx.x * R + r; i < NN; i += gridDim.x * R) {
        float v = y[(size_t)i * FO + c];
        s += v;
        q += v * v;
    }
    ssum[threadIdx.x] = s;
    ssq[threadIdx.x] = q;
    __syncthreads();
    if (r == 0) {
#pragma unroll
        for (int k = 1; k < R; k++) {
            s += ssum[k * FO + c];
            q += ssq[k * FO + c];
        }
        atomicAdd(&d_stats[c], s);
        atomicAdd(&d_stats[128 + c], q);
    }
}

template <int FO>
__global__ void k_bnparams(const float* __restrict__ gam,
                           const float* __restrict__ bet) {
    int c = threadIdx.x;
    if (c >= FO) return;
    float m   = d_stats[c] * (1.0f / NN);
    float var = d_stats[128 + c] * (1.0f / NN) - m * m;
    float sc  = gam[c] * rsqrtf(var + BN_EPS);
    d_scale[c] = sc;
    d_shift[c] = bet[c] - m * sc;
    d_stats[c] = 0.0f;            // reset for next layer
    d_stats[128 + c] = 0.0f;
}

// ---------------- graph boundaries (batch_index is sorted) ----------------
__global__ void k_bounds(const void* bi) {
    int i = blockIdx.x * blockDim.x + threadIdx.x;
    if (i >= NN) return;
    int g, gp, gn;
    if (d_is64_batch) {
        const long long* p = (const long long*)bi;
        g  = (int)p[i];
        gp = (i > 0)      ? (int)p[i - 1] : -1;
        gn = (i < NN - 1) ? (int)p[i + 1] : NG;
    } else {
        const int* p = (const int*)bi;
        g  = p[i];
        gp = (i > 0)      ? p[i - 1] : -1;
        gn = (i < NN - 1) ? p[i + 1] : NG;
    }
    if (g != gp) d_gstart[g] = i;
    if (g != gn) d_gend[g] = i + 1;
}

// ---------------- per-graph max pool (BN folded, no atomics) ----------------
__global__ void k_pool(const float* __restrict__ y3) {
    int g = blockIdx.x, c = threadIdx.x;
    float sc = d_scale[c], sh = d_shift[c];
    float m = -CUDART_INF_F;
    int s = d_gstart[g], e = d_gend[g];
    int i = s;
    for (; i + 4 <= e; i += 4) {
        float v0 = y3[(size_t)(i + 0) * 128 + c];
        float v1 = y3[(size_t)(i + 1) * 128 + c];
        float v2 = y3[(size_t)(i + 2) * 128 + c];
        float v3 = y3[(size_t)(i + 3) * 128 + c];
        m = fmaxf(m, fmaxf(fmaxf(v0, v1), fmaxf(v2, v3)));
    }
    for (; i < e; i++) m = fmaxf(m, y3[(size_t)i * 128 + c]);
    d_pool[g * 128 + c] = m * sc + sh;
}

// ---------------- final linear + log_softmax ----------------
__global__ void k_final(const float* __restrict__ Wl, const float* __restrict__ bl,
                        float* __restrict__ out) {
    __shared__ float ssum[12];
    int g = blockIdx.x, t = threadIdx.x;
    float p = d_pool[g * 128 + t];
    float a0 = p * Wl[t * 3 + 0];
    float a1 = p * Wl[t * 3 + 1];
    float a2 = p * Wl[t * 3 + 2];
#pragma unroll
    for (int o = 16; o > 0; o >>= 1) {
        a0 += __shfl_down_sync(0xFFFFFFFFu, a0, o);
        a1 += __shfl_down_sync(0xFFFFFFFFu, a1, o);
        a2 += __shfl_down_sync(0xFFFFFFFFu, a2, o);
    }
    int w = t >> 5;
    if ((t & 31) == 0) { ssum[w * 3] = a0; ssum[w * 3 + 1] = a1; ssum[w * 3 + 2] = a2; }
    __syncthreads();
    if (t == 0) {
        float l0 = bl[0], l1 = bl[1], l2 = bl[2];
#pragma unroll
        for (int k = 0; k < 4; k++) {
            l0 += ssum[k * 3]; l1 += ssum[k * 3 + 1]; l2 += ssum[k * 3 + 2];
        }
        float mx = fmaxf(l0, fmaxf(l1, l2));
        float lse = mx + logf(expf(l0 - mx) + expf(l1 - mx) + expf(l2 - mx));
        out[g * 3 + 0] = l0 - lse;
        out[g * 3 + 1] = l1 - lse;
        out[g * 3 + 2] = l2 - lse;
    }
}

// ---------------- launcher ----------------
extern "C" void kernel_launch(void* const* d_in, const int* in_sizes, int n_in,
                              void* d_out, int out_size) {
    const float* x   = (const float*)d_in[0];
    const void*  ei  = d_in[1];
    const void*  bi  = d_in[2];
    const float* W1  = (const float*)d_in[3];
    const float* b1  = (const float*)d_in[4];
    const float* g1  = (const float*)d_in[5];
    const float* be1 = (const float*)d_in[6];
    const float* W2  = (const float*)d_in[7];
    const float* b2  = (const float*)d_in[8];
    const float* g2  = (const float*)d_in[9];
    const float* be2 = (const float*)d_in[10];
    const float* W3  = (const float*)d_in[11];
    const float* b3  = (const float*)d_in[12];
    const float* g3  = (const float*)d_in[13];
    const float* be3 = (const float*)d_in[14];
    const float* Wl  = (const float*)d_in[15];
    const float* bl  = (const float*)d_in[16];
    float* out = (float*)d_out;

    float *y1, *y2, *y3;
    cudaGetSymbolAddress((void**)&y1, d_y1);
    cudaGetSymbolAddress((void**)&y2, d_y2);
    cudaGetSymbolAddress((void**)&y3, d_y3);

    const int T = 256;
    const int EB = (NE + T - 1) / T;

    k_detect<<<1, 32>>>(ei, bi);
    k_init<<<NBLK, T>>>();

    // CSR build
    k_count<<<EB, T>>>(ei);
    k_scan1<<<NBLK, T>>>();
    k_scan2<<<1, 512>>>();
    k_scan3<<<NBLK, T>>>();
    k_fill<<<EB, T>>>(ei);

    // layer 1: 2 -> 8
    k_agg2<<<NBLK, T>>>(x);
    k_gemm<2, 8><<<NBLK, T>>>(W1, b1, y1);
    k_stats<8><<<512, T>>>(y1);
    k_bnparams<8><<<1, 8>>>(g1, be1);

    // layer 2: 8 -> 32
    k_agg8<<<(NN * 8 + T - 1) / T, T>>>(y1);
    k_gemm<8, 32><<<NBLK, T>>>(W2, b2, y2);
    k_stats<32><<<512, T>>>(y2);
    k_bnparams<32><<<1, 32>>>(g2, be2);

    // layer 3: 32 -> 128
    k_agg32<<<(NN * 32 + T - 1) / T, T>>>(y2);
    k_gemm<32, 128><<<NBLK, T>>>(W3, b3, y3);
    k_stats<128><<<512, T>>>(y3);
    k_bnparams<128><<<1, 128>>>(g3, be3);

    // pooling + head
    k_bounds<<<NBLK, T>>>(bi);
    k_pool<<<NG, 128>>>(y3);
    k_final<<<NG, 128>>>(Wl, bl, out);
}

// round 6
// speedup vs baseline: 1.6033x; 1.0206x over previous
#include <cuda_runtime.h>
#include <math_constants.h>

// ---------------- problem constants ----------------
#define NN 100000      // nodes
#define NE 3200000     // edges
#define NG 512         // graphs
#define BN_EPS 1e-5f
#define NBLK ((NN + 255) / 256)   // 391

// ---------------- device scratch (no allocs allowed) ----------------
__device__ int      d_cnt[NN];
__device__ int      d_rowptr[NN + 1];
__device__ int      d_wp[NN];
__device__ int      d_bsum[512];
__device__ int      d_boff[512];
__device__ float2   d_csr[NE];            // (src as int bits, norm)
__device__ float    d_dis[NN];
__device__ float    d_y1 [(size_t)NN * 8];
__device__ float    d_y2 [(size_t)NN * 32];
__device__ float    d_y3 [(size_t)NN * 128];
__device__ float    d_stats[256];         // zero at load; reset after each use
__device__ float    d_scale[128];
__device__ float    d_shift[128];
__device__ int      d_gstart[NG];
__device__ int      d_gend[NG];
__device__ int      d_is64_edge;
__device__ int      d_is64_batch;
__device__ int      d_tick;               // zero at load; reset by last block

// ---------------- dtype detection ----------------
__global__ void k_detect(const void* ei, const void* bi) {
    if (threadIdx.x == 0 && blockIdx.x == 0) {
        const long long* e64 = (const long long*)ei;
        int ok = 1;
        for (int k = 0; k < 256; k++) {
            long long v = e64[k * 6000];
            if (v < 0 || v >= NN) { ok = 0; break; }
        }
        d_is64_edge = ok;
        const long long* b64 = (const long long*)bi;
        ok = 1;
        for (int k = 0; k < 256; k++) {
            long long v = b64[k * 195];
            if (v < 0 || v >= NG) { ok = 0; break; }
        }
        d_is64_batch = ok;
    }
}

// ---------------- init counters + graph boundaries (batch sorted) ----------------
__global__ void k_initbounds(const void* bi) {
    int i = blockIdx.x * blockDim.x + threadIdx.x;
    if (i >= NN) return;
    d_cnt[i] = 0;
    int g, gp, gn;
    if (d_is64_batch) {
        const long long* p = (const long long*)bi;
        g  = (int)p[i];
        gp = (i > 0)      ? (int)p[i - 1] : -1;
        gn = (i < NN - 1) ? (int)p[i + 1] : NG;
    } else {
        const int* p = (const int*)bi;
        g  = p[i];
        gp = (i > 0)      ? p[i - 1] : -1;
        gn = (i < NN - 1) ? p[i + 1] : NG;
    }
    if (g != gp) d_gstart[g] = i;
    if (g != gn) d_gend[g] = i + 1;
}

// ---------------- CSR build ----------------
__global__ void k_count(const void* ei) {
    int e = blockIdx.x * blockDim.x + threadIdx.x;
    if (e >= NE) return;
    int d;
    if (d_is64_edge) d = (int)((const long long*)ei)[(size_t)NE + e];
    else             d = ((const int*)ei)[NE + e];
    atomicAdd(&d_cnt[d], 1);
}

__global__ void k_scan1() {
    __shared__ int s[256];
    int i = blockIdx.x * 256 + threadIdx.x;
    int v = (i < NN) ? d_cnt[i] : 0;
    s[threadIdx.x] = v;
    __syncthreads();
    for (int o = 128; o > 0; o >>= 1) {
        if (threadIdx.x < o) s[threadIdx.x] += s[threadIdx.x + o];
        __syncthreads();
    }
    if (threadIdx.x == 0) d_bsum[blockIdx.x] = s[0];
}

__global__ void k_scan2() {
    __shared__ int s[512];
    int t = threadIdx.x;
    int orig = (t < NBLK) ? d_bsum[t] : 0;
    s[t] = orig;
    __syncthreads();
    for (int o = 1; o < 512; o <<= 1) {
        int u = (t >= o) ? s[t - o] : 0;
        __syncthreads();
        s[t] += u;
        __syncthreads();
    }
    d_boff[t] = s[t] - orig;
}

__global__ void k_scan3() {
    __shared__ int s[256];
    int i = blockIdx.x * 256 + threadIdx.x;
    int orig = (i < NN) ? d_cnt[i] : 0;
    s[threadIdx.x] = orig;
    __syncthreads();
    for (int o = 1; o < 256; o <<= 1) {
        int u = (threadIdx.x >= o) ? s[threadIdx.x - o] : 0;
        __syncthreads();
        s[threadIdx.x] += u;
        __syncthreads();
    }
    int excl = s[threadIdx.x] - orig + d_boff[blockIdx.x];
    if (i < NN) {
        d_rowptr[i] = excl;
        d_wp[i] = excl;
        d_dis[i] = rsqrtf((float)(orig + 1));
    }
    if (i == 0) d_rowptr[NN] = NE;
}

__global__ void k_fill(const void* ei) {
    int e = blockIdx.x * blockDim.x + threadIdx.x;
    if (e >= NE) return;
    int s, d;
    if (d_is64_edge) {
        const long long* p = (const long long*)ei;
        s = (int)p[e];
        d = (int)p[(size_t)NE + e];
    } else {
        const int* p = (const int*)ei;
        s = p[e];
        d = p[NE + e];
    }
    int pos = atomicAdd(&d_wp[d], 1);
    d_csr[pos] = make_float2(__int_as_float(s), d_dis[s] * d_dis[d]);
}

// ---------------- layer 1 fused: agg(F=2) + GEMM 2->8 + relu ----------------
__global__ void k_l1(const float* __restrict__ x,
                     const float* __restrict__ W1, const float* __restrict__ b1) {
    __shared__ float sW[16], sb[8];
    if (threadIdx.x < 16) sW[threadIdx.x] = W1[threadIdx.x];
    if (threadIdx.x < 8)  sb[threadIdx.x] = b1[threadIdx.x];
    __syncthreads();
    int i = blockIdx.x * blockDim.x + threadIdx.x;
    if (i >= NN) return;
    const float2* x2 = (const float2*)x;
    float di = d_dis[i];
    float2 self = x2[i];
    float ax = self.x * di * di, ay = self.y * di * di;
    int e = d_rowptr[i], end = d_rowptr[i + 1];
    for (; e + 4 <= end; e += 4) {
        float2 p0 = __ldg(&d_csr[e]),     p1 = __ldg(&d_csr[e + 1]);
        float2 p2 = __ldg(&d_csr[e + 2]), p3 = __ldg(&d_csr[e + 3]);
        float2 v0 = __ldg(&x2[__float_as_int(p0.x)]);
        float2 v1 = __ldg(&x2[__float_as_int(p1.x)]);
        float2 v2 = __ldg(&x2[__float_as_int(p2.x)]);
        float2 v3 = __ldg(&x2[__float_as_int(p3.x)]);
        ax += v0.x * p0.y + v1.x * p1.y + v2.x * p2.y + v3.x * p3.y;
        ay += v0.y * p0.y + v1.y * p1.y + v2.y * p2.y + v3.y * p3.y;
    }
    for (; e < end; e++) {
        float2 p = __ldg(&d_csr[e]);
        float2 v = __ldg(&x2[__float_as_int(p.x)]);
        ax += v.x * p.y;
        ay += v.y * p.y;
    }
    float4 o0, o1;
    o0.x = fmaxf(ax * sW[0] + ay * sW[8]  + sb[0], 0.f);
    o0.y = fmaxf(ax * sW[1] + ay * sW[9]  + sb[1], 0.f);
    o0.z = fmaxf(ax * sW[2] + ay * sW[10] + sb[2], 0.f);
    o0.w = fmaxf(ax * sW[3] + ay * sW[11] + sb[3], 0.f);
    o1.x = fmaxf(ax * sW[4] + ay * sW[12] + sb[4], 0.f);
    o1.y = fmaxf(ax * sW[5] + ay * sW[13] + sb[5], 0.f);
    o1.z = fmaxf(ax * sW[6] + ay * sW[14] + sb[6], 0.f);
    o1.w = fmaxf(ax * sW[7] + ay * sW[15] + sb[7], 0.f);
    float4* yo = (float4*)(d_y1 + (size_t)i * 8);
    yo[0] = o0;
    yo[1] = o1;
}

// ---------------- layer 2 fused: agg(F=8, BN folded) + GEMM 8->32 + relu ----------------
__global__ void k_l2(const float* __restrict__ W2, const float* __restrict__ b2) {
    __shared__ float sW[8 * 32], sb[32];
    for (int k = threadIdx.x; k < 256; k += blockDim.x) sW[k] = W2[k];
    if (threadIdx.x < 32) sb[threadIdx.x] = b2[threadIdx.x];
    __syncthreads();
    int lane = threadIdx.x & 31;
    int sub  = lane >> 3;
    int ln   = lane & 7;
    int gwarp  = (blockIdx.x * blockDim.x + threadIdx.x) >> 5;
    int nwarps = (gridDim.x * blockDim.x) >> 5;
    float sc = d_scale[ln], sh = d_shift[ln];
    for (int n0 = gwarp * 4; n0 < NN; n0 += nwarps * 4) {
        int node = n0 + sub;
        bool act = node < NN;
        int e = 0, end = 0;
        float acc = 0.f;
        if (act) {
            float di = d_dis[node];
            e = d_rowptr[node];
            end = d_rowptr[node + 1];
            acc = fmaf(d_y1[(size_t)node * 8 + ln], sc, sh) * di * di;
        }
        for (; e + 4 <= end; e += 4) {
            float2 p0 = __ldg(&d_csr[e]),     p1 = __ldg(&d_csr[e + 1]);
            float2 p2 = __ldg(&d_csr[e + 2]), p3 = __ldg(&d_csr[e + 3]);
            float h0 = __ldg(&d_y1[(size_t)__float_as_int(p0.x) * 8 + ln]);
            float h1 = __ldg(&d_y1[(size_t)__float_as_int(p1.x) * 8 + ln]);
            float h2 = __ldg(&d_y1[(size_t)__float_as_int(p2.x) * 8 + ln]);
            float h3 = __ldg(&d_y1[(size_t)__float_as_int(p3.x) * 8 + ln]);
            acc = fmaf(fmaf(h0, sc, sh), p0.y, acc);
            acc = fmaf(fmaf(h1, sc, sh), p1.y, acc);
            acc = fmaf(fmaf(h2, sc, sh), p2.y, acc);
            acc = fmaf(fmaf(h3, sc, sh), p3.y, acc);
        }
        for (; e < end; e++) {
            float2 p = __ldg(&d_csr[e]);
            float hv = __ldg(&d_y1[(size_t)__float_as_int(p.x) * 8 + ln]);
            acc = fmaf(fmaf(hv, sc, sh), p.y, acc);
        }
        float4 yv = make_float4(sb[ln * 4], sb[ln * 4 + 1], sb[ln * 4 + 2], sb[ln * 4 + 3]);
#pragma unroll
        for (int f = 0; f < 8; f++) {
            float av = __shfl_sync(0xFFFFFFFFu, acc, f, 8);
            const float* wr = &sW[f * 32 + ln * 4];
            yv.x = fmaf(av, wr[0], yv.x);
            yv.y = fmaf(av, wr[1], yv.y);
            yv.z = fmaf(av, wr[2], yv.z);
            yv.w = fmaf(av, wr[3], yv.w);
        }
        yv.x = fmaxf(yv.x, 0.f); yv.y = fmaxf(yv.y, 0.f);
        yv.z = fmaxf(yv.z, 0.f); yv.w = fmaxf(yv.w, 0.f);
        if (act) ((float4*)(d_y2 + (size_t)node * 32))[ln] = yv;
    }
}

// ---------------- layer 3 fused: agg(F=32, BN folded) + GEMM 32->128 + relu ----------------
__global__ void k_l3(const float* __restrict__ W3, const float* __restrict__ b3) {
    __shared__ float4 sW4[32 * 32];
    __shared__ float  sb[128];
    for (int k = threadIdx.x; k < 1024; k += blockDim.x)
        sW4[k] = ((const float4*)W3)[k];
    if (threadIdx.x < 128) sb[threadIdx.x] = b3[threadIdx.x];
    __syncthreads();
    int lane = threadIdx.x & 31;
    int gwarp  = (blockIdx.x * blockDim.x + threadIdx.x) >> 5;
    int nwarps = (gridDim.x * blockDim.x) >> 5;
    float sc = d_scale[lane], sh = d_shift[lane];
    for (int node = gwarp; node < NN; node += nwarps) {
        float di = d_dis[node];
        int e = d_rowptr[node], end = d_rowptr[node + 1];
        float acc = fmaf(d_y2[(size_t)node * 32 + lane], sc, sh) * di * di;
        for (; e + 4 <= end; e += 4) {
            float2 p0 = __ldg(&d_csr[e]),     p1 = __ldg(&d_csr[e + 1]);
            float2 p2 = __ldg(&d_csr[e + 2]), p3 = __ldg(&d_csr[e + 3]);
            float h0 = __ldg(&d_y2[(size_t)__float_as_int(p0.x) * 32 + lane]);
            float h1 = __ldg(&d_y2[(size_t)__float_as_int(p1.x) * 32 + lane]);
            float h2 = __ldg(&d_y2[(size_t)__float_as_int(p2.x) * 32 + lane]);
            float h3 = __ldg(&d_y2[(size_t)__float_as_int(p3.x) * 32 + lane]);
            acc = fmaf(fmaf(h0, sc, sh), p0.y, acc);
            acc = fmaf(fmaf(h1, sc, sh), p1.y, acc);
            acc = fmaf(fmaf(h2, sc, sh), p2.y, acc);
            acc = fmaf(fmaf(h3, sc, sh), p3.y, acc);
        }
        for (; e < end; e++) {
            float2 p = __ldg(&d_csr[e]);
            float hv = __ldg(&d_y2[(size_t)__float_as_int(p.x) * 32 + lane]);
            acc = fmaf(fmaf(hv, sc, sh), p.y, acc);
        }
        float4 yv = make_float4(sb[lane * 4], sb[lane * 4 + 1],
                                sb[lane * 4 + 2], sb[lane * 4 + 3]);
#pragma unroll
        for (int f = 0; f < 32; f++) {
            float av = __shfl_sync(0xFFFFFFFFu, acc, f);
            float4 w = sW4[f * 32 + lane];
            yv.x = fmaf(av, w.x, yv.x);
            yv.y = fmaf(av, w.y, yv.y);
            yv.z = fmaf(av, w.z, yv.z);
            yv.w = fmaf(av, w.w, yv.w);
        }
        yv.x = fmaxf(yv.x, 0.f); yv.y = fmaxf(yv.y, 0.f);
        yv.z = fmaxf(yv.z, 0.f); yv.w = fmaxf(yv.w, 0.f);
        ((float4*)(d_y3 + (size_t)node * 128))[lane] = yv;
    }
}

// ---------------- BN stats + fused params (last-block epilogue) ----------------
template <int FO>
__global__ void k_stats(const float* __restrict__ y,
                        const float* __restrict__ gam,
                        const float* __restrict__ bet) {
    constexpr int R = 256 / FO;
    __shared__ float ssum[256], ssq[256];
    int c = threadIdx.x % FO;
    int r = threadIdx.x / FO;
    float s = 0.f, q = 0.f;
    for (int i = blockIdx.x * R + r; i < NN; i += gridDim.x * R) {
        float v = y[(size_t)i * FO + c];
        s += v;
        q += v * v;
    }
    ssum[threadIdx.x] = s;
    ssq[threadIdx.x] = q;
    __syncthreads();
    if (r == 0) {
#pragma unroll
        for (int k = 1; k < R; k++) {
            s += ssum[k * FO + c];
            q += ssq[k * FO + c];
        }
        atomicAdd(&d_stats[c], s);
        atomicAdd(&d_stats[128 + c], q);
    }
    __threadfence();
    __shared__ int isLast;
    if (threadIdx.x == 0) isLast = (atomicAdd(&d_tick, 1) == (int)gridDim.x - 1);
    __syncthreads();
    if (isLast) {
        if (threadIdx.x < FO) {
            int cc = threadIdx.x;
            float sum = atomicAdd(&d_stats[cc], 0.f);
            float sq  = atomicAdd(&d_stats[128 + cc], 0.f);
            float m   = sum * (1.0f / NN);
            float var = sq * (1.0f / NN) - m * m;
            float scv = gam[cc] * rsqrtf(var + BN_EPS);
            d_scale[cc] = scv;
            d_shift[cc] = bet[cc] - m * scv;
            d_stats[cc] = 0.f;
            d_stats[128 + cc] = 0.f;
        }
        if (threadIdx.x == 0) d_tick = 0;
    }
}

// ---------------- fused max-pool (BN folded) + linear + log_softmax ----------------
__global__ void k_poolhead(const float* __restrict__ Wl, const float* __restrict__ bl,
                           float* __restrict__ out) {
    __shared__ float ssum[12];
    int g = blockIdx.x, t = threadIdx.x;
    float sc = d_scale[t], sh = d_shift[t];
    float m = -CUDART_INF_F;
    int s = d_gstart[g], e = d_gend[g];
    int i = s;
    for (; i + 4 <= e; i += 4) {
        float v0 = d_y3[(size_t)(i + 0) * 128 + t];
        float v1 = d_y3[(size_t)(i + 1) * 128 + t];
        float v2 = d_y3[(size_t)(i + 2) * 128 + t];
        float v3 = d_y3[(size_t)(i + 3) * 128 + t];
        m = fmaxf(m, fmaxf(fmaxf(v0, v1), fmaxf(v2, v3)));
    }
    for (; i < e; i++) m = fmaxf(m, d_y3[(size_t)i * 128 + t]);
    float p = fmaf(m, sc, sh);
    float a0 = p * Wl[t * 3 + 0];
    float a1 = p * Wl[t * 3 + 1];
    float a2 = p * Wl[t * 3 + 2];
#pragma unroll
    for (int o = 16; o > 0; o >>= 1) {
        a0 += __shfl_down_sync(0xFFFFFFFFu, a0, o);
        a1 += __shfl_down_sync(0xFFFFFFFFu, a1, o);
        a2 += __shfl_down_sync(0xFFFFFFFFu, a2, o);
    }
    int w = t >> 5;
    if ((t & 31) == 0) { ssum[w * 3] = a0; ssum[w * 3 + 1] = a1; ssum[w * 3 + 2] = a2; }
    __syncthreads();
    if (t == 0) {
        float l0 = bl[0], l1 = bl[1], l2 = bl[2];
#pragma unroll
        for (int k = 0; k < 4; k++) {
            l0 += ssum[k * 3]; l1 += ssum[k * 3 + 1]; l2 += ssum[k * 3 + 2];
        }
        float mx = fmaxf(l0, fmaxf(l1, l2));
        float lse = mx + logf(expf(l0 - mx) + expf(l1 - mx) + expf(l2 - mx));
        out[g * 3 + 0] = l0 - lse;
        out[g * 3 + 1] = l1 - lse;
        out[g * 3 + 2] = l2 - lse;
    }
}

// ---------------- launcher ----------------
extern "C" void kernel_launch(void* const* d_in, const int* in_sizes, int n_in,
                              void* d_out, int out_size) {
    const float* x   = (const float*)d_in[0];
    const void*  ei  = d_in[1];
    const void*  bi  = d_in[2];
    const float* W1  = (const float*)d_in[3];
    const float* b1  = (const float*)d_in[4];
    const float* g1  = (const float*)d_in[5];
    const float* be1 = (const float*)d_in[6];
    const float* W2  = (const float*)d_in[7];
    const float* b2  = (const float*)d_in[8];
    const float* g2  = (const float*)d_in[9];
    const float* be2 = (const float*)d_in[10];
    const float* W3  = (const float*)d_in[11];
    const float* b3  = (const float*)d_in[12];
    const float* g3  = (const float*)d_in[13];
    const float* be3 = (const float*)d_in[14];
    const float* Wl  = (const float*)d_in[15];
    const float* bl  = (const float*)d_in[16];
    float* out = (float*)d_out;

    // device symbol addresses (host code may NOT use __device__ symbols directly)
    float *y1, *y2, *y3;
    cudaGetSymbolAddress((void**)&y1, d_y1);
    cudaGetSymbolAddress((void**)&y2, d_y2);
    cudaGetSymbolAddress((void**)&y3, d_y3);

    const int T = 256;
    const int EB = (NE + T - 1) / T;
    const int G  = 592;

    k_detect<<<1, 32>>>(ei, bi);
    k_initbounds<<<NBLK, T>>>(bi);

    // CSR build
    k_count<<<EB, T>>>(ei);
    k_scan1<<<NBLK, T>>>();
    k_scan2<<<1, 512>>>();
    k_scan3<<<NBLK, T>>>();
    k_fill<<<EB, T>>>(ei);

    // layer 1: 2 -> 8
    k_l1<<<NBLK, T>>>(x, W1, b1);
    k_stats<8><<<256, T>>>(y1, g1, be1);

    // layer 2: 8 -> 32
    k_l2<<<G, T>>>(W2, b2);
    k_stats<32><<<256, T>>>(y2, g2, be2);

    // layer 3: 32 -> 128
    k_l3<<<G, T>>>(W3, b3);
    k_stats<128><<<256, T>>>(y3, g3, be3);

    // pooling + head
    k_poolhead<<<NG, 128>>>(Wl, bl, out);
}